// round 5
// baseline (speedup 1.0000x reference)
#include <cuda_runtime.h>
#include <cstdint>

#define B_DIM 2048
#define D_DIM 512
#define H_DIM 2048
#define NS    32

typedef unsigned long long ull;

// ---- scratch ----
__device__ float g_Wt[H_DIM * D_DIM];
__device__ int   g_samp[NS * B_DIM];
__device__ float g_temp[NS * B_DIM];

// ================= transpose W [512,2048] -> Wt [2048,512] =================
__global__ void transpose_kernel(const float* __restrict__ W) {
    __shared__ float tile[32][33];
    int bx = blockIdx.x * 32;
    int by = blockIdx.y * 32;
    int tx = threadIdx.x, ty = threadIdx.y;
#pragma unroll
    for (int k = 0; k < 32; k += 8)
        tile[ty + k][tx] = W[(size_t)(by + ty + k) * H_DIM + bx + tx];
    __syncthreads();
#pragma unroll
    for (int k = 0; k < 32; k += 8)
        g_Wt[(size_t)(bx + ty + k) * D_DIM + by + tx] = tile[tx][ty + k];
}

// ================= h = x @ W ================================================
#define GBM 128
#define GBN 128
#define GBK 8
__global__ __launch_bounds__(256) void gemm_kernel(const float* __restrict__ A,
                                                   const float* __restrict__ B,
                                                   float* __restrict__ C) {
    __shared__ float As[GBK][GBM];
    __shared__ float Bs[GBK][GBN];
    int tid = threadIdx.x;
    int bm = blockIdx.y * GBM;
    int bn = blockIdx.x * GBN;
    int ar = tid >> 1;
    int ac = (tid & 1) << 2;
    int br = tid >> 5;
    int bc = (tid & 31) << 2;
    int tx = (tid & 15) << 3;
    int ty = (tid >> 4) << 3;
    float acc[8][8] = {};
    for (int k0 = 0; k0 < D_DIM; k0 += GBK) {
        float4 a4 = *(const float4*)(A + (size_t)(bm + ar) * D_DIM + k0 + ac);
        As[ac + 0][ar] = a4.x; As[ac + 1][ar] = a4.y;
        As[ac + 2][ar] = a4.z; As[ac + 3][ar] = a4.w;
        float4 b4 = *(const float4*)(B + (size_t)(k0 + br) * H_DIM + bn + bc);
        *(float4*)&Bs[br][bc] = b4;
        __syncthreads();
#pragma unroll
        for (int kk = 0; kk < GBK; ++kk) {
            float ra[8], rb[8];
            *(float4*)(ra)     = *(const float4*)&As[kk][ty];
            *(float4*)(ra + 4) = *(const float4*)&As[kk][ty + 4];
            *(float4*)(rb)     = *(const float4*)&Bs[kk][tx];
            *(float4*)(rb + 4) = *(const float4*)&Bs[kk][tx + 4];
#pragma unroll
            for (int i = 0; i < 8; ++i)
#pragma unroll
                for (int j = 0; j < 8; ++j)
                    acc[i][j] = fmaf(ra[i], rb[j], acc[i][j]);
        }
        __syncthreads();
    }
#pragma unroll
    for (int i = 0; i < 8; ++i)
#pragma unroll
        for (int j = 0; j < 8; j += 4)
            *(float4*)(C + (size_t)(bm + ty + i) * H_DIM + bn + tx + j) = *(float4*)&acc[i][j];
}

// ================= softmax ===================================================
__global__ __launch_bounds__(256) void softmax_kernel(const float* __restrict__ h,
                                                      float* __restrict__ z) {
    int b = blockIdx.x;
    int t = threadIdx.x;
    const float* row = h + (size_t)b * H_DIM;
    float v[8];
    float mx = -3.4e38f;
#pragma unroll
    for (int k = 0; k < 8; ++k) { v[k] = row[t + (k << 8)]; mx = fmaxf(mx, v[k]); }
    __shared__ float red[256];
    red[t] = mx; __syncthreads();
    for (int s = 128; s; s >>= 1) { if (t < s) red[t] = fmaxf(red[t], red[t + s]); __syncthreads(); }
    mx = red[0]; __syncthreads();
    float sum = 0.f;
#pragma unroll
    for (int k = 0; k < 8; ++k) { v[k] = expf(v[k] - mx); sum += v[k]; }
    red[t] = sum; __syncthreads();
    for (int s = 128; s; s >>= 1) { if (t < s) red[t] += red[t + s]; __syncthreads(); }
    sum = red[0];
    float* zr = z + (size_t)b * H_DIM;
#pragma unroll
    for (int k = 0; k < 8; ++k) zr[t + (k << 8)] = v[k] / sum;
}

// ====== JAX threefry2x32 partitionable: key (0,42), ctr (0,L), bits = x0^x1 ==
__device__ __forceinline__ uint32_t draw_bits(uint32_t L) {
    const uint32_t ks1 = 42u;
    const uint32_t ks2 = 0x1BD11BDAu ^ 42u;  // 0x1BD11BF0
    uint32_t x0 = 0u;            // c0(=0) + ks0(=0)
    uint32_t x1 = L + ks1;
#define TFR(r) { x0 += x1; x1 = __funnelshift_l(x1, x1, (r)); x1 ^= x0; }
    TFR(13) TFR(15) TFR(26) TFR(6)   x0 += ks1; x1 += ks2 + 1u;
    TFR(17) TFR(29) TFR(16) TFR(24)  x0 += ks2; x1 += 2u;
    TFR(13) TFR(15) TFR(26) TFR(6)               x1 += ks1 + 3u;
    TFR(17) TFR(29) TFR(16) TFR(24)  x0 += ks1; x1 += ks2 + 4u;
    TFR(13) TFR(15) TFR(26) TFR(6)   x0 += ks2; x1 += 5u;
#undef TFR
    return x0 ^ x1;              // xor-fold of the two output words
}

// insert into descending sorted top-4
__device__ __forceinline__ void ins4(ull t[4], ull k) {
    if (k <= t[3]) return;
    if (k > t[0])      { t[3] = t[2]; t[2] = t[1]; t[1] = t[0]; t[0] = k; }
    else if (k > t[1]) { t[3] = t[2]; t[2] = t[1]; t[1] = k; }
    else if (k > t[2]) { t[3] = t[2]; t[2] = k; }
    else               { t[3] = k; }
}

__device__ __forceinline__ int resolve_row(ull t[4], int lane,
                                           const float* __restrict__ zrow) {
    ull mykey = 0ull;
#pragma unroll
    for (int s = 0; s < 4; ++s) {
        ull mine = t[0];
        ull m = mine;
#pragma unroll
        for (int off = 16; off; off >>= 1) {
            ull o = __shfl_down_sync(0xffffffffu, m, off);
            if (o > m) m = o;
        }
        m = __shfl_sync(0xffffffffu, m, 0);
        if (mine == m && m != 0ull) { t[0] = t[1]; t[1] = t[2]; t[2] = t[3]; t[3] = 0ull; }
        if (lane == s) mykey = m;
    }
    float sc = -3.4e38f;
    uint32_t hidx = 0xffffffffu;
    if (lane < 4 && mykey != 0ull) {
        uint32_t v = (uint32_t)(mykey >> 11);
        hidx = 2047u - (uint32_t)(mykey & 2047u);
        // JAX uniform: f = bitcast((bits>>9)|0x3f800000) - 1 ; u = max(f, tiny)
        float f = __uint_as_float(v | 0x3f800000u) - 1.0f;
        float u = fmaxf(f, 1.17549435e-38f);
        float g = -logf(-logf(u));
        sc = g + zrow[hidx];
    }
#pragma unroll
    for (int off = 1; off < 4; off <<= 1) {
        float    so = __shfl_xor_sync(0xffffffffu, sc, off);
        uint32_t ho = __shfl_xor_sync(0xffffffffu, hidx, off);
        if (so > sc || (so == sc && ho < hidx)) { sc = so; hidx = ho; }
    }
    return (int)__shfl_sync(0xffffffffu, hidx, 0);
}

// one warp per slot w = n*2048 + b
__global__ __launch_bounds__(256) void categorical_kernel(const float* __restrict__ z) {
    int w    = blockIdx.x * 8 + (threadIdx.x >> 5);   // 0..65535
    int lane = threadIdx.x & 31;
    int b = w & 2047;
    ull t[4] = {0, 0, 0, 0};
    uint32_t base = (uint32_t)w << 11;
#pragma unroll 2
    for (int it = 0; it < 64; ++it) {
        uint32_t hh = (uint32_t)lane + ((uint32_t)it << 5);
        uint32_t o = draw_bits(base + hh);
        ins4(t, ((ull)(o >> 9) << 11) | (ull)(2047u - hh));
    }
    int i0 = resolve_row(t, lane, z + (size_t)b * H_DIM);
    if (lane == 0) g_samp[w] = i0;
}

// ================= one-hot scatter ==========================================
__global__ void scatter_ones(float* __restrict__ onehot) {
    int t = blockIdx.x * 256 + threadIdx.x;
    int i = t >> 11, j = t & 2047;
    // faithful .T.reshape scramble: samp[i,j] = c[j%32, i*64 + j/32]
    int s = g_samp[((j & 31) << 11) | ((i << 6) + (j >> 5))];
    onehot[((size_t)t << 11) + (size_t)s] = 1.0f;
}

// ================= decode gather + gaussian temp ============================
__global__ __launch_bounds__(256) void decode_kernel(const float* __restrict__ x,
                                                     float* __restrict__ xdec) {
    int w    = blockIdx.x * 8 + (threadIdx.x >> 5);
    int lane = threadIdx.x & 31;
    int i = w >> 11, j = w & 2047;
    int s = g_samp[((j & 31) << 11) | ((i << 6) + (j >> 5))];
    const float4* wr = (const float4*)(g_Wt + (size_t)s * D_DIM);
    const float4* xr = (const float4*)(x + (size_t)j * D_DIM);
    float4* od = (float4*)(xdec + (size_t)w * D_DIM);
    float ssd = 0.f;
#pragma unroll
    for (int tt = 0; tt < 4; ++tt) {
        int idx = lane + (tt << 5);
        float4 a = xr[idx], c = wr[idx];
        od[idx] = c;
        float dx = a.x - c.x, dy = a.y - c.y, dz = a.z - c.z, dw = a.w - c.w;
        ssd += dx * dx + dy * dy + dz * dz + dw * dw;
    }
#pragma unroll
    for (int off = 16; off; off >>= 1) ssd += __shfl_xor_sync(0xffffffffu, ssd, off);
    if (lane == 0) g_temp[w] = 0.3989422804014327f * expf(-0.5f * ssd);
}

// ================= weight ====================================================
__global__ void weight_kernel(float* __restrict__ wout) {
    int j = blockIdx.x * 256 + threadIdx.x;
    float tv[NS];
    float sum = 0.f;
#pragma unroll
    for (int i = 0; i < NS; ++i) { tv[i] = g_temp[(size_t)i * B_DIM + j]; sum += tv[i]; }
    float mean = sum * (1.0f / 32.0f);
#pragma unroll
    for (int i = 0; i < NS; ++i) wout[(size_t)i * B_DIM + j] = tv[i] / mean;
}

// ================= launch ====================================================
extern "C" void kernel_launch(void* const* d_in, const int* in_sizes, int n_in,
                              void* d_out, int out_size) {
    const float* x = (const float*)d_in[0];
    const float* W = (const float*)d_in[1];
    float* out = (float*)d_out;

    float* h    = out;
    float* z    = out + (size_t)4194304;
    float* oh   = out + (size_t)8388608;
    float* xdec = out + (size_t)142606336;
    float* wt   = out + (size_t)176160768;

    transpose_kernel<<<dim3(64, 16), dim3(32, 8)>>>(W);
    gemm_kernel<<<dim3(16, 16), 256>>>(x, W, h);
    softmax_kernel<<<2048, 256>>>(h, z);
    categorical_kernel<<<8192, 256>>>(z);
    cudaMemsetAsync(oh, 0, (size_t)134217728 * sizeof(float));
    scatter_ones<<<256, 256>>>(oh);
    decode_kernel<<<8192, 256>>>(x, xdec);
    weight_kernel<<<8, 256>>>(wt);
}

// round 6
// speedup vs baseline: 1.1547x; 1.1547x over previous
#include <cuda_runtime.h>
#include <cstdint>

#define B_DIM 2048
#define D_DIM 512
#define H_DIM 2048
#define NS    32

typedef unsigned long long ull;

// ---- scratch ----
__device__ float g_Wt[H_DIM * D_DIM];     // W transposed [2048][512]
__device__ ull   g_cand[NS * B_DIM * 4];  // top-4 keys per slot
__device__ int   g_samp[NS * B_DIM];      // resolved sample index per slot
__device__ float g_temp[NS * B_DIM];      // gaussian temp[i][j]

// ====== JAX threefry2x32 partitionable: key (0,42), ctr (0,L), bits = x0^x1 ==
__device__ __forceinline__ uint32_t draw_bits(uint32_t L) {
    const uint32_t ks1 = 42u;
    const uint32_t ks2 = 0x1BD11BDAu ^ 42u;  // 0x1BD11BF0
    uint32_t x0 = 0u;            // c0(=0) + ks0(=0)
    uint32_t x1 = L + ks1;
#define TFR(r) { x0 += x1; x1 = __funnelshift_l(x1, x1, (r)); x1 ^= x0; }
    TFR(13) TFR(15) TFR(26) TFR(6)   x0 += ks1; x1 += ks2 + 1u;
    TFR(17) TFR(29) TFR(16) TFR(24)  x0 += ks2; x1 += 2u;
    TFR(13) TFR(15) TFR(26) TFR(6)               x1 += ks1 + 3u;
    TFR(17) TFR(29) TFR(16) TFR(24)  x0 += ks1; x1 += ks2 + 4u;
    TFR(13) TFR(15) TFR(26) TFR(6)   x0 += ks2; x1 += 5u;
#undef TFR
    return x0 ^ x1;
}

// insert into descending sorted top-4 (keys unique by idx bits)
__device__ __forceinline__ void ins4(ull t[4], ull k) {
    if (k <= t[3]) return;
    if (k > t[0])      { t[3] = t[2]; t[2] = t[1]; t[1] = t[0]; t[0] = k; }
    else if (k > t[1]) { t[3] = t[2]; t[2] = t[1]; t[1] = k; }
    else if (k > t[2]) { t[3] = t[2]; t[2] = k; }
    else               { t[3] = k; }
}

// ================= MEGA kernel: track + gemm + transpose + zero =============
// 12288 blocks, role by bid%12: 0-7 track, 8 gemm(64x64), 9 transpose, 10-11 zero
__global__ __launch_bounds__(256, 6) void mega_kernel(const float* __restrict__ x,
                                                      const float* __restrict__ W,
                                                      float* __restrict__ h,
                                                      float* __restrict__ oh) {
    __shared__ float sm[1088];
    int bid = blockIdx.x;
    int l = bid % 12;
    int g = bid / 12;        // 0..1023
    int tid = threadIdx.x;

    if (l < 8) {
        // ---------------- track: one warp per slot ----------------
        int w    = (g * 8 + l) * 8 + (tid >> 5);   // 0..65535
        int lane = tid & 31;
        ull t[4] = {0, 0, 0, 0};
        uint32_t base = (uint32_t)w << 11;
#pragma unroll 2
        for (int it = 0; it < 64; ++it) {
            uint32_t hh = (uint32_t)lane + ((uint32_t)it << 5);
            uint32_t o = draw_bits(base + hh);
            ins4(t, ((ull)o << 32) | (ull)(2047u - hh));   // reg-pair key, no shifts
        }
        // merge per-lane top4 -> warp top4, store candidates
#pragma unroll
        for (int s = 0; s < 4; ++s) {
            ull mine = t[0];
            ull m = mine;
#pragma unroll
            for (int off = 16; off; off >>= 1) {
                ull o = __shfl_down_sync(0xffffffffu, m, off);
                if (o > m) m = o;
            }
            m = __shfl_sync(0xffffffffu, m, 0);
            if (mine == m && m != 0ull) { t[0] = t[1]; t[1] = t[2]; t[2] = t[3]; t[3] = 0ull; }
            if (lane == 0) g_cand[(size_t)w * 4 + s] = m;
        }
    } else if (l == 8) {
        // ---------------- gemm: 64x64 tile, 4x4 microtile ----------------
        float* As = sm;          // [8][64]
        float* Bs = sm + 512;    // [8][64]
        int bm = (g >> 5) << 6;
        int bn = (g & 31) << 6;
        int ar = tid >> 2;            // 0..63
        int ac = (tid & 3) << 1;      // 0,2,4,6
        int br = tid >> 5;            // 0..7
        int bc = (tid & 31) << 1;     // 0..62
        int tx = (tid & 15) << 2;
        int ty = (tid >> 4) << 2;
        float acc[4][4] = {};
        for (int k0 = 0; k0 < D_DIM; k0 += 8) {
            float2 a2 = *(const float2*)(x + (size_t)(bm + ar) * D_DIM + k0 + ac);
            As[ac * 64 + ar]       = a2.x;
            As[(ac + 1) * 64 + ar] = a2.y;
            float2 b2 = *(const float2*)(W + (size_t)(k0 + br) * H_DIM + bn + bc);
            *(float2*)&Bs[br * 64 + bc] = b2;
            __syncthreads();
#pragma unroll
            for (int kk = 0; kk < 8; ++kk) {
                float ra[4], rb[4];
                *(float4*)ra = *(const float4*)&As[kk * 64 + ty];
                *(float4*)rb = *(const float4*)&Bs[kk * 64 + tx];
#pragma unroll
                for (int i = 0; i < 4; ++i)
#pragma unroll
                    for (int j = 0; j < 4; ++j)
                        acc[i][j] = fmaf(ra[i], rb[j], acc[i][j]);
            }
            __syncthreads();
        }
#pragma unroll
        for (int i = 0; i < 4; ++i)
            *(float4*)(h + (size_t)(bm + ty + i) * H_DIM + bn + tx) = *(float4*)&acc[i][0];
    } else if (l == 9) {
        // ---------------- transpose W -> Wt ----------------
        float* tile = sm;  // 32x33
        int bx = (g & 63) << 5;   // H
        int by = (g >> 6) << 5;   // D
        int tx = tid & 31, ty = tid >> 5;  // ty 0..7
#pragma unroll
        for (int k = 0; k < 32; k += 8)
            tile[(ty + k) * 33 + tx] = W[(size_t)(by + ty + k) * H_DIM + bx + tx];
        __syncthreads();
#pragma unroll
        for (int k = 0; k < 32; k += 8)
            g_Wt[(size_t)(bx + ty + k) * D_DIM + by + tx] = tile[tx * 33 + ty + k];
    } else {
        // ---------------- zero onehot: 256 KB per block ----------------
        int zid = (g << 1) + (l - 10);   // 0..2047
        float4* p = (float4*)(oh + (size_t)zid * 65536);
        float4 zf = make_float4(0.f, 0.f, 0.f, 0.f);
#pragma unroll
        for (int m = 0; m < 64; ++m) p[tid + (m << 8)] = zf;
    }
}

// ================= softmax ===================================================
__global__ __launch_bounds__(256) void softmax_kernel(const float* __restrict__ h,
                                                      float* __restrict__ z) {
    int b = blockIdx.x;
    int t = threadIdx.x;
    const float* row = h + (size_t)b * H_DIM;
    float v[8];
    float mx = -3.4e38f;
#pragma unroll
    for (int k = 0; k < 8; ++k) { v[k] = row[t + (k << 8)]; mx = fmaxf(mx, v[k]); }
    __shared__ float red[256];
    red[t] = mx; __syncthreads();
    for (int s = 128; s; s >>= 1) { if (t < s) red[t] = fmaxf(red[t], red[t + s]); __syncthreads(); }
    mx = red[0]; __syncthreads();
    float sum = 0.f;
#pragma unroll
    for (int k = 0; k < 8; ++k) { v[k] = expf(v[k] - mx); sum += v[k]; }
    red[t] = sum; __syncthreads();
    for (int s = 128; s; s >>= 1) { if (t < s) red[t] += red[t + s]; __syncthreads(); }
    sum = red[0];
    float* zr = z + (size_t)b * H_DIM;
#pragma unroll
    for (int k = 0; k < 8; ++k) zr[t + (k << 8)] = v[k] / sum;
}

// ================= resolve: exact-score 4 candidates per slot ================
__global__ __launch_bounds__(256) void resolve_kernel(const float* __restrict__ z) {
    int w = blockIdx.x * 256 + threadIdx.x;   // 0..65535
    int b = w & 2047;
    float best = -3.4e38f;
    uint32_t bidx = 0xffffffffu;
#pragma unroll
    for (int s = 0; s < 4; ++s) {
        ull key = g_cand[(size_t)w * 4 + s];
        if (key == 0ull) continue;
        uint32_t o   = (uint32_t)(key >> 32);
        uint32_t idx = 2047u - (uint32_t)(key & 2047u);
        // JAX uniform: f = bitcast((bits>>9)|0x3f800000) - 1 ; u = max(f, tiny)
        float f = __uint_as_float((o >> 9) | 0x3f800000u) - 1.0f;
        float u = fmaxf(f, 1.17549435e-38f);
        float sc = -logf(-logf(u)) + z[(size_t)b * H_DIM + idx];
        if (sc > best || (sc == best && idx < bidx)) { best = sc; bidx = idx; }
    }
    g_samp[w] = (int)bidx;
}

// ========== decode gather + gaussian temp + fused one-hot scatter ============
__global__ __launch_bounds__(256) void decode_kernel(const float* __restrict__ x,
                                                     float* __restrict__ xdec,
                                                     float* __restrict__ oh) {
    int w    = blockIdx.x * 8 + (threadIdx.x >> 5);  // 0..65535
    int lane = threadIdx.x & 31;
    int i = w >> 11, j = w & 2047;
    // faithful .T.reshape scramble: samp[i,j] = c[j%32, i*64 + j/32]
    int s = g_samp[((j & 31) << 11) | ((i << 6) + (j >> 5))];
    const float4* wr = (const float4*)(g_Wt + (size_t)s * D_DIM);
    const float4* xr = (const float4*)(x + (size_t)j * D_DIM);
    float4* od = (float4*)(xdec + (size_t)w * D_DIM);
    float ssd = 0.f;
#pragma unroll
    for (int tt = 0; tt < 4; ++tt) {
        int idx = lane + (tt << 5);
        float4 a = xr[idx], c = wr[idx];
        od[idx] = c;
        float dx = a.x - c.x, dy = a.y - c.y, dz = a.z - c.z, dw = a.w - c.w;
        ssd += dx * dx + dy * dy + dz * dz + dw * dw;
    }
#pragma unroll
    for (int off = 16; off; off >>= 1) ssd += __shfl_xor_sync(0xffffffffu, ssd, off);
    if (lane == 0) {
        g_temp[w] = 0.3989422804014327f * expf(-0.5f * ssd);
        oh[((size_t)w << 11) + (size_t)s] = 1.0f;    // fused scatter
    }
}

// ================= weight ====================================================
__global__ void weight_kernel(float* __restrict__ wout) {
    int j = blockIdx.x * 256 + threadIdx.x;
    float tv[NS];
    float sum = 0.f;
#pragma unroll
    for (int i = 0; i < NS; ++i) { tv[i] = g_temp[(size_t)i * B_DIM + j]; sum += tv[i]; }
    float mean = sum * (1.0f / 32.0f);
#pragma unroll
    for (int i = 0; i < NS; ++i) wout[(size_t)i * B_DIM + j] = tv[i] / mean;
}

// ================= launch ====================================================
extern "C" void kernel_launch(void* const* d_in, const int* in_sizes, int n_in,
                              void* d_out, int out_size) {
    const float* x = (const float*)d_in[0];
    const float* W = (const float*)d_in[1];
    float* out = (float*)d_out;

    float* h    = out;
    float* z    = out + (size_t)4194304;
    float* oh   = out + (size_t)8388608;
    float* xdec = out + (size_t)142606336;
    float* wt   = out + (size_t)176160768;

    mega_kernel<<<12288, 256>>>(x, W, h, oh);
    softmax_kernel<<<2048, 256>>>(h, z);
    resolve_kernel<<<256, 256>>>(z);
    decode_kernel<<<8192, 256>>>(x, xdec, oh);
    weight_kernel<<<8, 256>>>(wt);
}

// round 8
// speedup vs baseline: 1.1819x; 1.0236x over previous
#include <cuda_runtime.h>
#include <cstdint>

#define B_DIM 2048
#define D_DIM 512
#define H_DIM 2048
#define NS    32

typedef unsigned long long ull;

// ---- scratch ----
__device__ float g_Wt[H_DIM * D_DIM];     // W transposed [2048][512]
__device__ ull   g_cand[NS * B_DIM * 4];  // top-4 keys per slot
__device__ int   g_samp[NS * B_DIM];      // resolved sample index per slot
__device__ float g_temp[NS * B_DIM];      // gaussian temp[i][j]

// ================= tf32 helpers =============================================
__device__ __forceinline__ uint32_t tf32_of(float f) {
    uint32_t u;
    asm("cvt.rna.tf32.f32 %0, %1;" : "=r"(u) : "f"(f));
    return u;
}

#define MMA_TF32(c, A0, A1, A2, A3, B0, B1) \
    asm volatile("mma.sync.aligned.m16n8k8.row.col.f32.tf32.tf32.f32 " \
                 "{%0,%1,%2,%3},{%4,%5,%6,%7},{%8,%9},{%0,%1,%2,%3};" \
                 : "+f"((c)[0]), "+f"((c)[1]), "+f"((c)[2]), "+f"((c)[3]) \
                 : "r"(A0), "r"(A1), "r"(A2), "r"(A3), "r"(B0), "r"(B1))

// ======== h = x @ W : tf32 3-term split, 128x128 tile, K chunks of 16 =======
#define KC 16
#define LDP 136   // padded row stride (floats)
__global__ __launch_bounds__(256) void gemm_mma(const float* __restrict__ x,
                                                const float* __restrict__ W,
                                                float* __restrict__ h) {
    __shared__ uint32_t Ah[KC * LDP], Al[KC * LDP], Bh[KC * LDP], Bl[KC * LDP];
    int tid  = threadIdx.x;
    int bm   = (int)(blockIdx.x >> 4) << 7;
    int bn   = (int)(blockIdx.x & 15) << 7;
    int wid  = tid >> 5, lane = tid & 31;
    int grp  = lane >> 2, tig = lane & 3;
    int moff = (wid >> 2) << 6;   // 0 / 64
    int noff = (wid & 3) << 5;    // 0,32,64,96
    float acc[4][4][4] = {};

    for (int k0 = 0; k0 < D_DIM; k0 += KC) {
        __syncthreads();
        // stage A[128 rows][16 k] -> Ah/Al[k][m]
#pragma unroll 1
        for (int i = tid; i < 512; i += 256) {
            int row = i >> 2, c0 = (i & 3) << 2;
            float4 v = *(const float4*)(x + (size_t)(bm + row) * D_DIM + k0 + c0);
            float f[4] = {v.x, v.y, v.z, v.w};
#pragma unroll
            for (int j = 0; j < 4; ++j) {
                uint32_t hi = tf32_of(f[j]);
                Ah[(c0 + j) * LDP + row] = hi;
                Al[(c0 + j) * LDP + row] = tf32_of(f[j] - __uint_as_float(hi));
            }
        }
        // stage B[16 k][128 n] -> Bh/Bl[k][n]
#pragma unroll 1
        for (int i = tid; i < 512; i += 256) {
            int kr = i >> 5, c0 = (i & 31) << 2;
            float4 v = *(const float4*)(W + (size_t)(k0 + kr) * H_DIM + bn + c0);
            float f[4] = {v.x, v.y, v.z, v.w};
#pragma unroll
            for (int j = 0; j < 4; ++j) {
                uint32_t hi = tf32_of(f[j]);
                Bh[kr * LDP + c0 + j] = hi;
                Bl[kr * LDP + c0 + j] = tf32_of(f[j] - __uint_as_float(hi));
            }
        }
        __syncthreads();
#pragma unroll
        for (int ks = 0; ks < KC; ks += 8) {
            uint32_t ah[4][4], al[4][4];
#pragma unroll
            for (int mt = 0; mt < 4; ++mt) {
                int m0 = moff + mt * 16 + grp;
                ah[mt][0] = Ah[(ks + tig) * LDP + m0];
                ah[mt][1] = Ah[(ks + tig) * LDP + m0 + 8];
                ah[mt][2] = Ah[(ks + tig + 4) * LDP + m0];
                ah[mt][3] = Ah[(ks + tig + 4) * LDP + m0 + 8];
                al[mt][0] = Al[(ks + tig) * LDP + m0];
                al[mt][1] = Al[(ks + tig) * LDP + m0 + 8];
                al[mt][2] = Al[(ks + tig + 4) * LDP + m0];
                al[mt][3] = Al[(ks + tig + 4) * LDP + m0 + 8];
            }
#pragma unroll
            for (int nt = 0; nt < 4; ++nt) {
                int n0 = noff + nt * 8 + grp;
                uint32_t b0h = Bh[(ks + tig) * LDP + n0];
                uint32_t b1h = Bh[(ks + tig + 4) * LDP + n0];
                uint32_t b0l = Bl[(ks + tig) * LDP + n0];
                uint32_t b1l = Bl[(ks + tig + 4) * LDP + n0];
#pragma unroll
                for (int mt = 0; mt < 4; ++mt) {
                    MMA_TF32(acc[mt][nt], ah[mt][0], ah[mt][1], ah[mt][2], ah[mt][3], b0h, b1h);
                    MMA_TF32(acc[mt][nt], ah[mt][0], ah[mt][1], ah[mt][2], ah[mt][3], b0l, b1l);
                    MMA_TF32(acc[mt][nt], al[mt][0], al[mt][1], al[mt][2], al[mt][3], b0h, b1h);
                }
            }
        }
    }
    // epilogue
#pragma unroll
    for (int mt = 0; mt < 4; ++mt) {
#pragma unroll
        for (int nt = 0; nt < 4; ++nt) {
            int row = bm + moff + mt * 16 + grp;
            int col = bn + noff + nt * 8 + 2 * tig;
            *(float2*)(h + (size_t)row * H_DIM + col) =
                make_float2(acc[mt][nt][0], acc[mt][nt][1]);
            *(float2*)(h + (size_t)(row + 8) * H_DIM + col) =
                make_float2(acc[mt][nt][2], acc[mt][nt][3]);
        }
    }
}

// ====== JAX threefry2x32 partitionable: key (0,42), ctr (0,L), bits = x0^x1 ==
__device__ __forceinline__ uint32_t draw_bits(uint32_t L) {
    const uint32_t ks1 = 42u;
    const uint32_t ks2 = 0x1BD11BDAu ^ 42u;
    uint32_t x0 = 0u;
    uint32_t x1 = L + ks1;
#define TFR(r) { x0 += x1; x1 = __funnelshift_l(x1, x1, (r)); x1 ^= x0; }
    TFR(13) TFR(15) TFR(26) TFR(6)   x0 += ks1; x1 += ks2 + 1u;
    TFR(17) TFR(29) TFR(16) TFR(24)  x0 += ks2; x1 += 2u;
    TFR(13) TFR(15) TFR(26) TFR(6)               x1 += ks1 + 3u;
    TFR(17) TFR(29) TFR(16) TFR(24)  x0 += ks1; x1 += ks2 + 4u;
    TFR(13) TFR(15) TFR(26) TFR(6)   x0 += ks2; x1 += 5u;
#undef TFR
    return x0 ^ x1;
}

__device__ __forceinline__ void ins4(ull t[4], ull k) {
    if (k <= t[3]) return;
    if (k > t[0])      { t[3] = t[2]; t[2] = t[1]; t[1] = t[0]; t[0] = k; }
    else if (k > t[1]) { t[3] = t[2]; t[2] = t[1]; t[1] = k; }
    else if (k > t[2]) { t[3] = t[2]; t[2] = k; }
    else               { t[3] = k; }
}

// ======= MEGA: 12288 blocks, l=bid%12: 0-7 track, 8 transpose, 9 softmax(x2),
//         10-11 zero (grid-stride) ============================================
__global__ __launch_bounds__(256, 6) void mega_kernel(const float* __restrict__ h,
                                                      const float* __restrict__ W,
                                                      float* __restrict__ z,
                                                      float* __restrict__ oh) {
    __shared__ float sm[1088];
    int bid = blockIdx.x;
    int l = bid % 12;
    int g = bid / 12;        // 0..1023
    int tid = threadIdx.x;

    if (l < 8) {
        // ---------------- track: one warp per slot ----------------
        int w    = (g * 8 + l) * 8 + (tid >> 5);
        int lane = tid & 31;
        ull t[4] = {0, 0, 0, 0};
        uint32_t base = (uint32_t)w << 11;
#pragma unroll 2
        for (int it = 0; it < 64; ++it) {
            uint32_t hh = (uint32_t)lane + ((uint32_t)it << 5);
            uint32_t o = draw_bits(base + hh);
            ins4(t, ((ull)o << 32) | (ull)(2047u - hh));
        }
#pragma unroll
        for (int s = 0; s < 4; ++s) {
            ull mine = t[0];
            ull m = mine;
#pragma unroll
            for (int off = 16; off; off >>= 1) {
                ull o = __shfl_down_sync(0xffffffffu, m, off);
                if (o > m) m = o;
            }
            m = __shfl_sync(0xffffffffu, m, 0);
            if (mine == m && m != 0ull) { t[0] = t[1]; t[1] = t[2]; t[2] = t[3]; t[3] = 0ull; }
            if (lane == 0) g_cand[(size_t)w * 4 + s] = m;
        }
    } else if (l == 8) {
        // ---------------- transpose W -> Wt ----------------
        int bx = (g & 63) << 5;   // H
        int by = (g >> 6) << 5;   // D
        int tx = tid & 31, ty = tid >> 5;  // ty 0..7
#pragma unroll
        for (int k = 0; k < 32; k += 8)
            sm[(ty + k) * 33 + tx] = W[(size_t)(by + ty + k) * H_DIM + bx + tx];
        __syncthreads();
#pragma unroll
        for (int k = 0; k < 32; k += 8)
            g_Wt[(size_t)(bx + ty + k) * D_DIM + by + tx] = sm[tx * 33 + ty + k];
    } else if (l == 9) {
        // ---------------- softmax: rows 2g, 2g+1 ----------------
#pragma unroll 1
        for (int r = 0; r < 2; ++r) {
            int b = g * 2 + r;
            const float* row = h + (size_t)b * H_DIM;
            float v[8];
            float mx = -3.4e38f;
#pragma unroll
            for (int k = 0; k < 8; ++k) { v[k] = row[tid + (k << 8)]; mx = fmaxf(mx, v[k]); }
            sm[tid] = mx; __syncthreads();
            for (int s = 128; s; s >>= 1) { if (tid < s) sm[tid] = fmaxf(sm[tid], sm[tid + s]); __syncthreads(); }
            mx = sm[0]; __syncthreads();
            float sum = 0.f;
#pragma unroll
            for (int k = 0; k < 8; ++k) { v[k] = expf(v[k] - mx); sum += v[k]; }
            sm[tid] = sum; __syncthreads();
            for (int s = 128; s; s >>= 1) { if (tid < s) sm[tid] += sm[tid + s]; __syncthreads(); }
            sum = sm[0]; __syncthreads();
            float* zr = z + (size_t)b * H_DIM;
#pragma unroll
            for (int k = 0; k < 8; ++k) zr[tid + (k << 8)] = v[k] / sum;
        }
    } else {
        // ---------------- zero onehot (grid-stride float4) ----------------
        int zid = (l - 10) * 1024 + g;              // 0..2047
        float4* p = (float4*)oh;
        float4 zf = make_float4(0.f, 0.f, 0.f, 0.f);
        for (int i = zid * 256 + tid; i < 33554432; i += 2048 * 256) p[i] = zf;
    }
}

// ================= resolve: exact-score 4 candidates per slot ================
__global__ __launch_bounds__(256) void resolve_kernel(const float* __restrict__ z) {
    int w = blockIdx.x * 256 + threadIdx.x;
    int b = w & 2047;
    float best = -3.4e38f;
    uint32_t bidx = 0xffffffffu;
#pragma unroll
    for (int s = 0; s < 4; ++s) {
        ull key = g_cand[(size_t)w * 4 + s];
        if (key == 0ull) continue;
        uint32_t o   = (uint32_t)(key >> 32);
        uint32_t idx = 2047u - (uint32_t)(key & 2047u);
        float f = __uint_as_float((o >> 9) | 0x3f800000u) - 1.0f;
        float u = fmaxf(f, 1.17549435e-38f);
        float sc = -logf(-logf(u)) + z[(size_t)b * H_DIM + idx];
        if (sc > best || (sc == best && idx < bidx)) { best = sc; bidx = idx; }
    }
    g_samp[w] = (int)bidx;
}

// ========== decode gather + gaussian temp + fused one-hot scatter ============
__global__ __launch_bounds__(256) void decode_kernel(const float* __restrict__ x,
                                                     float* __restrict__ xdec,
                                                     float* __restrict__ oh) {
    int w    = blockIdx.x * 8 + (threadIdx.x >> 5);
    int lane = threadIdx.x & 31;
    int i = w >> 11, j = w & 2047;
    int s = g_samp[((j & 31) << 11) | ((i << 6) + (j >> 5))];
    const float4* wr = (const float4*)(g_Wt + (size_t)s * D_DIM);
    const float4* xr = (const float4*)(x + (size_t)j * D_DIM);
    float4* od = (float4*)(xdec + (size_t)w * D_DIM);
    float ssd = 0.f;
#pragma unroll
    for (int tt = 0; tt < 4; ++tt) {
        int idx = lane + (tt << 5);
        float4 a = xr[idx], c = wr[idx];
        od[idx] = c;
        float dx = a.x - c.x, dy = a.y - c.y, dz = a.z - c.z, dw = a.w - c.w;
        ssd += dx * dx + dy * dy + dz * dz + dw * dw;
    }
#pragma unroll
    for (int off = 16; off; off >>= 1) ssd += __shfl_xor_sync(0xffffffffu, ssd, off);
    if (lane == 0) {
        g_temp[w] = 0.3989422804014327f * expf(-0.5f * ssd);
        oh[((size_t)w << 11) + (size_t)s] = 1.0f;
    }
}

// ================= weight ====================================================
__global__ void weight_kernel(float* __restrict__ wout) {
    int j = blockIdx.x * 256 + threadIdx.x;
    float tv[NS];
    float sum = 0.f;
#pragma unroll
    for (int i = 0; i < NS; ++i) { tv[i] = g_temp[(size_t)i * B_DIM + j]; sum += tv[i]; }
    float mean = sum * (1.0f / 32.0f);
#pragma unroll
    for (int i = 0; i < NS; ++i) wout[(size_t)i * B_DIM + j] = tv[i] / mean;
}

// ================= launch ====================================================
extern "C" void kernel_launch(void* const* d_in, const int* in_sizes, int n_in,
                              void* d_out, int out_size) {
    const float* x = (const float*)d_in[0];
    const float* W = (const float*)d_in[1];
    float* out = (float*)d_out;

    float* h    = out;
    float* z    = out + (size_t)4194304;
    float* oh   = out + (size_t)8388608;
    float* xdec = out + (size_t)142606336;
    float* wt   = out + (size_t)176160768;

    gemm_mma<<<256, 256>>>(x, W, h);
    mega_kernel<<<12288, 256>>>(h, W, z, oh);
    resolve_kernel<<<256, 256>>>(z);
    decode_kernel<<<8192, 256>>>(x, xdec, oh);
    weight_kernel<<<8, 256>>>(wt);
}